// round 2
// baseline (speedup 1.0000x reference)
#include <cuda_runtime.h>
#include <cuda_bf16.h>

// GIN 2-layer GNN for GB300 (sm_103a)
// Layer l: agg = segment_sum(feat[src], dst); h = feat + agg;
//          out = relu( relu(h @ Wa + ba) @ Wb + bb )
// Layer1: 64 -> 128 -> 128 ; Layer2: 128 -> 128 -> 64

#define N_NODES 50000
#define N_EDGES 800000
#define DI 64
#define DH 128
#define DO 64

// Scratch (device globals; float4 to guarantee 16B alignment)
__device__ float4 g_agg1[N_NODES * DI / 4];   // 12.8 MB
__device__ float4 g_hmid[N_NODES * DH / 4];   // 25.6 MB
__device__ float4 g_agg2[N_NODES * DH / 4];   // 25.6 MB
__device__ int    g_is64;                     // 1 if edge_index is int64

// ---------------------------------------------------------------------------
// Zero aggregation buffers + reset dtype flag
// ---------------------------------------------------------------------------
__global__ void zero_kernel() {
    int i = blockIdx.x * blockDim.x + threadIdx.x;
    if (i == 0) g_is64 = 1;
    const int n1 = N_NODES * DI / 4;
    const int n2 = N_NODES * DH / 4;
    float4 z = make_float4(0.f, 0.f, 0.f, 0.f);
    if (i < n1) g_agg1[i] = z;
    if (i < n2) g_agg2[i] = z;
}

// ---------------------------------------------------------------------------
// Detect edge_index dtype. View the buffer as int64 over the first N_EDGES
// entries (safe: that's 6.4MB, <= the real buffer size for either dtype).
// If data is really int32, the int64 view yields values with a nonzero high
// word almost everywhere -> out of [0, N_NODES) -> flag int32.
// ---------------------------------------------------------------------------
__global__ void detect_kernel(const void* ei) {
    const long long* e64 = (const long long*)ei;
    int i = blockIdx.x * blockDim.x + threadIdx.x;
    if (i < N_EDGES) {
        long long v = e64[i];
        if (v < 0 || v >= N_NODES) g_is64 = 0;
    }
}

// ---------------------------------------------------------------------------
// Edge scatter: agg[dst] += feat[src], vector f32x4 global reduction
// ---------------------------------------------------------------------------
__device__ __forceinline__ void red_add_v4(float* addr, float4 v) {
    asm volatile("red.global.add.v4.f32 [%0], {%1,%2,%3,%4};"
                 :: "l"(addr), "f"(v.x), "f"(v.y), "f"(v.z), "f"(v.w)
                 : "memory");
}

template <int D>
__global__ void scatter_kernel(const float* __restrict__ feat,
                               const void* __restrict__ ei,
                               float* __restrict__ agg) {
    constexpr int C = D / 4;                    // float4 chunks per row
    int idx = blockIdx.x * blockDim.x + threadIdx.x;
    if (idx >= N_EDGES * C) return;
    int e = idx / C;
    int c = idx - e * C;

    long long s, d;
    if (g_is64) {
        const long long* e64 = (const long long*)ei;
        s = e64[e];
        d = e64[N_EDGES + e];
    } else {
        const int* e32 = (const int*)ei;
        s = e32[e];
        d = e32[N_EDGES + e];
    }
    // backstop against any malformed index
    if ((unsigned long long)s >= N_NODES || (unsigned long long)d >= N_NODES) return;

    float4 v = __ldg(reinterpret_cast<const float4*>(feat + s * (long long)D) + c);
    red_add_v4(agg + d * (long long)D + c * 4, v);
}

// ---------------------------------------------------------------------------
// Fused 2-linear MLP with GIN add:
//   row = in[r] + agg[r]
//   mid = relu(row @ Wa + ba)        (mid dim = 128 both layers)
//   out[r] = relu(mid @ Wb + bb)
// Weights staged in dynamic shared memory; 4 rows per block iteration.
// blockDim = 128.
// ---------------------------------------------------------------------------
template <int DIN, int DOUT>
__global__ void mlp_kernel(const float* __restrict__ in,
                           const float* __restrict__ agg,
                           const float* __restrict__ Wa,
                           const float* __restrict__ ba,
                           const float* __restrict__ Wb,
                           const float* __restrict__ bb,
                           float* __restrict__ out) {
    constexpr int R = 4;
    extern __shared__ float sm[];
    float* sWa  = sm;                   // DIN * 128
    float* sWb  = sWa + DIN * 128;      // 128 * DOUT
    float* sBa  = sWb + 128 * DOUT;     // 128
    float* sBb  = sBa + 128;            // DOUT
    float* sRow = sBb + DOUT;           // R * DIN
    float* sMid = sRow + R * DIN;       // R * 128

    const int t = threadIdx.x;          // 0..127

    // Stage weights/biases once per block
    for (int i = t; i < DIN * 128 / 4; i += 128)
        reinterpret_cast<float4*>(sWa)[i] = reinterpret_cast<const float4*>(Wa)[i];
    for (int i = t; i < 128 * DOUT / 4; i += 128)
        reinterpret_cast<float4*>(sWb)[i] = reinterpret_cast<const float4*>(Wb)[i];
    sBa[t] = ba[t];
    if (t < DOUT) sBb[t] = bb[t];
    __syncthreads();

    const int ntiles = (N_NODES + R - 1) / R;
    for (int tile = blockIdx.x; tile < ntiles; tile += gridDim.x) {
        const int r0 = tile * R;

        // Load R rows (with GIN self + agg add) into shared
        for (int i = t; i < R * DIN; i += 128) {
            int r = i / DIN, k = i - r * DIN;
            int row = r0 + r;
            float v = 0.f;
            if (row < N_NODES) {
                long long off = (long long)row * DIN + k;
                v = in[off] + agg[off];
            }
            sRow[i] = v;
        }
        __syncthreads();

        // Phase 1: mid[t] for each of R rows
        float acc[R];
#pragma unroll
        for (int r = 0; r < R; r++) acc[r] = sBa[t];
#pragma unroll
        for (int k = 0; k < DIN; k += 4) {
            float w0 = sWa[(k + 0) * 128 + t];
            float w1 = sWa[(k + 1) * 128 + t];
            float w2 = sWa[(k + 2) * 128 + t];
            float w3 = sWa[(k + 3) * 128 + t];
#pragma unroll
            for (int r = 0; r < R; r++) {
                float4 v = *reinterpret_cast<const float4*>(&sRow[r * DIN + k]);
                acc[r] += w0 * v.x;
                acc[r] += w1 * v.y;
                acc[r] += w2 * v.z;
                acc[r] += w3 * v.w;
            }
        }
#pragma unroll
        for (int r = 0; r < R; r++)
            sMid[r * 128 + t] = fmaxf(acc[r], 0.f);
        __syncthreads();

        // Phase 2: out. For DOUT=64 split threads into 2 groups covering rows.
        constexpr int G   = 128 / DOUT;   // 1 or 2 groups
        constexpr int RPG = R / G;        // rows per group
        const int grp = t / DOUT;
        const int to  = t - grp * DOUT;
        float acc2[RPG];
#pragma unroll
        for (int r = 0; r < RPG; r++) acc2[r] = sBb[to];
#pragma unroll
        for (int k = 0; k < 128; k += 4) {
            float w0 = sWb[(k + 0) * DOUT + to];
            float w1 = sWb[(k + 1) * DOUT + to];
            float w2 = sWb[(k + 2) * DOUT + to];
            float w3 = sWb[(k + 3) * DOUT + to];
#pragma unroll
            for (int r = 0; r < RPG; r++) {
                float4 v = *reinterpret_cast<const float4*>(&sMid[(grp * RPG + r) * 128 + k]);
                acc2[r] += w0 * v.x;
                acc2[r] += w1 * v.y;
                acc2[r] += w2 * v.z;
                acc2[r] += w3 * v.w;
            }
        }
#pragma unroll
        for (int r = 0; r < RPG; r++) {
            int row = r0 + grp * RPG + r;
            if (row < N_NODES)
                out[(long long)row * DOUT + to] = fmaxf(acc2[r], 0.f);
        }
        __syncthreads();
    }
}

// ---------------------------------------------------------------------------
// Launch
// ---------------------------------------------------------------------------
extern "C" void kernel_launch(void* const* d_in, const int* in_sizes, int n_in,
                              void* d_out, int out_size) {
    const float* x   = (const float*)d_in[0];
    const void*  ei  = d_in[1];                 // int32 or int64, detected on device
    const float* W1a = (const float*)d_in[2];
    const float* b1a = (const float*)d_in[3];
    const float* W1b = (const float*)d_in[4];
    const float* b1b = (const float*)d_in[5];
    const float* W2a = (const float*)d_in[6];
    const float* b2a = (const float*)d_in[7];
    const float* W2b = (const float*)d_in[8];
    const float* b2b = (const float*)d_in[9];
    float*       out = (float*)d_out;

    float *agg1, *hmid, *agg2;
    cudaGetSymbolAddress((void**)&agg1, g_agg1);
    cudaGetSymbolAddress((void**)&hmid, g_hmid);
    cudaGetSymbolAddress((void**)&agg2, g_agg2);

    // Dynamic shared sizes
    const int SMEM1 = (DI * 128 + 128 * DH + 128 + DH + 4 * DI + 4 * 128) * 4;
    const int SMEM2 = (DH * 128 + 128 * DO + 128 + DO + 4 * DH + 4 * 128) * 4;
    cudaFuncSetAttribute(mlp_kernel<DI, DH>,
                         cudaFuncAttributeMaxDynamicSharedMemorySize, SMEM1);
    cudaFuncSetAttribute(mlp_kernel<DH, DO>,
                         cudaFuncAttributeMaxDynamicSharedMemorySize, SMEM2);

    // 1. zero aggregation buffers + reset dtype flag
    {
        int n2 = N_NODES * DH / 4;
        zero_kernel<<<(n2 + 255) / 256, 256>>>();
    }
    // 2. detect edge_index dtype
    detect_kernel<<<(N_EDGES + 255) / 256, 256>>>(ei);
    // 3. layer-1 scatter (d=64)
    {
        int total = N_EDGES * (DI / 4);
        scatter_kernel<DI><<<(total + 255) / 256, 256>>>(x, ei, agg1);
    }
    // 4. layer-1 fused MLP -> hmid
    mlp_kernel<DI, DH><<<304, 128, SMEM1>>>(x, agg1, W1a, b1a, W1b, b1b, hmid);
    // 5. layer-2 scatter (d=128)
    {
        int total = N_EDGES * (DH / 4);
        scatter_kernel<DH><<<(total + 255) / 256, 256>>>(hmid, ei, agg2);
    }
    // 6. layer-2 fused MLP -> out
    mlp_kernel<DH, DO><<<304, 128, SMEM2>>>(hmid, agg2, W2a, b2a, W2b, b2b, out);
}

// round 3
// speedup vs baseline: 1.2771x; 1.2771x over previous
#include <cuda_runtime.h>
#include <cuda_bf16.h>

// GIN 2-layer GNN for GB300 (sm_103a)
// Layer l: agg = segment_sum(feat[src], dst); h = feat + agg;
//          out = relu( relu(h @ Wa + ba) @ Wb + bb )
// Layer1: 64 -> 128 -> 128 ; Layer2: 128 -> 128 -> 64

#define N_NODES 50000
#define N_EDGES 800000
#define DI 64
#define DH 128
#define DO 64

// Scratch (device globals; float4 to guarantee 16B alignment)
__device__ float4 g_agg1[N_NODES * DI / 4];   // 12.8 MB
__device__ float4 g_hmid[N_NODES * DH / 4];   // 25.6 MB
__device__ float4 g_agg2[N_NODES * DH / 4];   // 25.6 MB
__device__ int    g_is64;                     // 1 if edge_index is int64

// ---------------------------------------------------------------------------
// Zero aggregation buffers + reset dtype flag
// ---------------------------------------------------------------------------
__global__ void zero_kernel() {
    int i = blockIdx.x * blockDim.x + threadIdx.x;
    if (i == 0) g_is64 = 1;
    const int n1 = N_NODES * DI / 4;
    const int n2 = N_NODES * DH / 4;
    float4 z = make_float4(0.f, 0.f, 0.f, 0.f);
    if (i < n1) g_agg1[i] = z;
    if (i < n2) g_agg2[i] = z;
}

// ---------------------------------------------------------------------------
// Detect edge_index dtype (int32 data viewed as int64 lands out of range)
// ---------------------------------------------------------------------------
__global__ void detect_kernel(const void* ei) {
    const long long* e64 = (const long long*)ei;
    int i = blockIdx.x * blockDim.x + threadIdx.x;
    if (i < N_EDGES) {
        long long v = e64[i];
        if (v < 0 || v >= N_NODES) g_is64 = 0;
    }
}

// ---------------------------------------------------------------------------
// Edge scatter: agg[dst] += feat[src], vector f32x4 global reduction
// ---------------------------------------------------------------------------
__device__ __forceinline__ void red_add_v4(float* addr, float4 v) {
    asm volatile("red.global.add.v4.f32 [%0], {%1,%2,%3,%4};"
                 :: "l"(addr), "f"(v.x), "f"(v.y), "f"(v.z), "f"(v.w)
                 : "memory");
}

template <int D>
__global__ void scatter_kernel(const float* __restrict__ feat,
                               const void* __restrict__ ei,
                               float* __restrict__ agg) {
    constexpr int C = D / 4;                    // float4 chunks per row
    int idx = blockIdx.x * blockDim.x + threadIdx.x;
    if (idx >= N_EDGES * C) return;
    int e = idx / C;
    int c = idx - e * C;

    long long s, d;
    if (g_is64) {
        const long long* e64 = (const long long*)ei;
        s = e64[e];
        d = e64[N_EDGES + e];
    } else {
        const int* e32 = (const int*)ei;
        s = e32[e];
        d = e32[N_EDGES + e];
    }
    if ((unsigned long long)s >= N_NODES || (unsigned long long)d >= N_NODES) return;

    float4 v = __ldg(reinterpret_cast<const float4*>(feat + s * (long long)D) + c);
    red_add_v4(agg + d * (long long)D + c * 4, v);
}

// ---------------------------------------------------------------------------
// Fused 2-linear MLP with GIN add.
// blockDim = 256: two independent 128-thread row-groups share the staged
// weights. Each group processes RG=8 rows per tile iteration.
// sMid aliases sRow (extra barrier) to keep smem <= ~107.5KB -> 2 blocks/SM.
// ---------------------------------------------------------------------------
template <int DIN, int DOUT>
__global__ void __launch_bounds__(256, 2)
mlp_kernel(const float* __restrict__ in,
           const float* __restrict__ agg,
           const float* __restrict__ Wa,
           const float* __restrict__ ba,
           const float* __restrict__ Wb,
           const float* __restrict__ bb,
           float* __restrict__ out) {
    constexpr int NG = 2;                 // row groups per block
    constexpr int RG = 8;                 // rows per group
    constexpr int RT = NG * RG;           // rows per block tile = 16
    constexpr int BUF = RT * (DIN > 128 ? DIN : 128);

    extern __shared__ float sm[];
    float* sWa  = sm;                     // DIN * 128
    float* sWb  = sWa + DIN * 128;        // 128 * DOUT
    float* sBa  = sWb + 128 * DOUT;       // 128
    float* sBb  = sBa + 128;              // DOUT
    float* sBuf = sBb + DOUT;             // BUF floats (rows, then mid)

    const int t  = threadIdx.x;           // 0..255
    const int g  = t >> 7;                // row group 0/1
    const int lt = t & 127;               // lane within group

    // Stage weights/biases once per block (256 threads)
    for (int i = t; i < DIN * 128 / 4; i += 256)
        reinterpret_cast<float4*>(sWa)[i] = reinterpret_cast<const float4*>(Wa)[i];
    for (int i = t; i < 128 * DOUT / 4; i += 256)
        reinterpret_cast<float4*>(sWb)[i] = reinterpret_cast<const float4*>(Wb)[i];
    if (t < 128) sBa[t] = ba[t];
    if (t < DOUT) sBb[t] = bb[t];
    __syncthreads();

    const int ntiles = (N_NODES + RT - 1) / RT;
    for (int tile = blockIdx.x; tile < ntiles; tile += gridDim.x) {
        const int r0 = tile * RT;

        // Load RT rows (with GIN self + agg add) into sBuf (row-major [RT][DIN])
        for (int i = t; i < RT * DIN; i += 256) {
            int r = i / DIN, k = i - r * DIN;
            int row = r0 + r;
            float v = 0.f;
            if (row < N_NODES) {
                long long off = (long long)row * DIN + k;
                v = in[off] + agg[off];
            }
            sBuf[i] = v;
        }
        __syncthreads();

        // Phase 1: mid[lt] for RG rows of this group
        float acc[RG];
#pragma unroll
        for (int r = 0; r < RG; r++) acc[r] = sBa[lt];
#pragma unroll
        for (int k = 0; k < DIN; k += 4) {
            float w0 = sWa[(k + 0) * 128 + lt];
            float w1 = sWa[(k + 1) * 128 + lt];
            float w2 = sWa[(k + 2) * 128 + lt];
            float w3 = sWa[(k + 3) * 128 + lt];
#pragma unroll
            for (int r = 0; r < RG; r++) {
                float4 v = *reinterpret_cast<const float4*>(&sBuf[(g * RG + r) * DIN + k]);
                acc[r] += w0 * v.x;
                acc[r] += w1 * v.y;
                acc[r] += w2 * v.z;
                acc[r] += w3 * v.w;
            }
        }
        __syncthreads();   // all reads of sBuf(rows) done before overwrite

        // Write mid = relu(acc) into sBuf (now [RT][128])
#pragma unroll
        for (int r = 0; r < RG; r++)
            sBuf[(g * RG + r) * 128 + lt] = fmaxf(acc[r], 0.f);
        __syncthreads();

        // Phase 2: out. For DOUT=64 split the 128 group-threads into 2 subgroups.
        constexpr int G2  = 128 / DOUT;   // 1 or 2
        constexpr int RPG = RG / G2;      // rows per subgroup (8 or 4)
        const int grp = lt / DOUT;
        const int to  = lt - grp * DOUT;
        float acc2[RPG];
#pragma unroll
        for (int r = 0; r < RPG; r++) acc2[r] = sBb[to];
#pragma unroll
        for (int k = 0; k < 128; k += 4) {
            float w0 = sWb[(k + 0) * DOUT + to];
            float w1 = sWb[(k + 1) * DOUT + to];
            float w2 = sWb[(k + 2) * DOUT + to];
            float w3 = sWb[(k + 3) * DOUT + to];
#pragma unroll
            for (int r = 0; r < RPG; r++) {
                float4 v = *reinterpret_cast<const float4*>(
                    &sBuf[(g * RG + grp * RPG + r) * 128 + k]);
                acc2[r] += w0 * v.x;
                acc2[r] += w1 * v.y;
                acc2[r] += w2 * v.z;
                acc2[r] += w3 * v.w;
            }
        }
#pragma unroll
        for (int r = 0; r < RPG; r++) {
            int row = r0 + g * RG + grp * RPG + r;
            if (row < N_NODES)
                out[(long long)row * DOUT + to] = fmaxf(acc2[r], 0.f);
        }
        __syncthreads();
    }
}

// ---------------------------------------------------------------------------
// Launch
// ---------------------------------------------------------------------------
extern "C" void kernel_launch(void* const* d_in, const int* in_sizes, int n_in,
                              void* d_out, int out_size) {
    const float* x   = (const float*)d_in[0];
    const void*  ei  = d_in[1];                 // int32 or int64, detected on device
    const float* W1a = (const float*)d_in[2];
    const float* b1a = (const float*)d_in[3];
    const float* W1b = (const float*)d_in[4];
    const float* b1b = (const float*)d_in[5];
    const float* W2a = (const float*)d_in[6];
    const float* b2a = (const float*)d_in[7];
    const float* W2b = (const float*)d_in[8];
    const float* b2b = (const float*)d_in[9];
    float*       out = (float*)d_out;

    float *agg1, *hmid, *agg2;
    cudaGetSymbolAddress((void**)&agg1, g_agg1);
    cudaGetSymbolAddress((void**)&hmid, g_hmid);
    cudaGetSymbolAddress((void**)&agg2, g_agg2);

    // Dynamic shared sizes (floats): weights + biases + row/mid buffer
    const int RT = 16;
    const int SMEM1 = (DI * 128 + 128 * DH + 128 + DH + RT * 128) * 4;  // ~107.5KB
    const int SMEM2 = (DH * 128 + 128 * DO + 128 + DO + RT * 128) * 4;  // ~107.3KB
    cudaFuncSetAttribute(mlp_kernel<DI, DH>,
                         cudaFuncAttributeMaxDynamicSharedMemorySize, SMEM1);
    cudaFuncSetAttribute(mlp_kernel<DH, DO>,
                         cudaFuncAttributeMaxDynamicSharedMemorySize, SMEM2);

    // 1. zero aggregation buffers + reset dtype flag
    {
        int n2 = N_NODES * DH / 4;
        zero_kernel<<<(n2 + 255) / 256, 256>>>();
    }
    // 2. detect edge_index dtype
    detect_kernel<<<(N_EDGES + 255) / 256, 256>>>(ei);
    // 3. layer-1 scatter (d=64)
    {
        int total = N_EDGES * (DI / 4);
        scatter_kernel<DI><<<(total + 255) / 256, 256>>>(x, ei, agg1);
    }
    // 4. layer-1 fused MLP -> hmid
    mlp_kernel<DI, DH><<<296, 256, SMEM1>>>(x, agg1, W1a, b1a, W1b, b1b, hmid);
    // 5. layer-2 scatter (d=128)
    {
        int total = N_EDGES * (DH / 4);
        scatter_kernel<DH><<<(total + 255) / 256, 256>>>(hmid, ei, agg2);
    }
    // 6. layer-2 fused MLP -> out
    mlp_kernel<DH, DO><<<296, 256, SMEM2>>>(hmid, agg2, W2a, b2a, W2b, b2b, out);
}

// round 4
// speedup vs baseline: 1.3677x; 1.0709x over previous
#include <cuda_runtime.h>
#include <cuda_bf16.h>

// GIN 2-layer GNN for GB300 (sm_103a)
#define N_NODES 50000
#define N_EDGES 800000
#define DI 64
#define DH 128
#define DO 64

// Scratch (device globals; float4 to guarantee 16B alignment)
__device__ float4 g_agg1[N_NODES * DI / 4];   // 12.8 MB
__device__ float4 g_hmid[N_NODES * DH / 4];   // 25.6 MB
__device__ float4 g_agg2[N_NODES * DH / 4];   // 25.6 MB
__device__ int    g_is64;                     // 1 if edge_index is int64

// ---------------------------------------------------------------------------
__global__ void zero_kernel() {
    int i = blockIdx.x * blockDim.x + threadIdx.x;
    if (i == 0) g_is64 = 1;
    const int n1 = N_NODES * DI / 4;
    const int n2 = N_NODES * DH / 4;
    float4 z = make_float4(0.f, 0.f, 0.f, 0.f);
    if (i < n1) g_agg1[i] = z;
    if (i < n2) g_agg2[i] = z;
}

__global__ void detect_kernel(const void* ei) {
    const long long* e64 = (const long long*)ei;
    int i = blockIdx.x * blockDim.x + threadIdx.x;
    if (i < N_EDGES) {
        long long v = e64[i];
        if (v < 0 || v >= N_NODES) g_is64 = 0;
    }
}

// ---------------------------------------------------------------------------
// Edge scatter: agg[dst] += feat[src], vector f32x4 global reduction
// ---------------------------------------------------------------------------
__device__ __forceinline__ void red_add_v4(float* addr, float4 v) {
    asm volatile("red.global.add.v4.f32 [%0], {%1,%2,%3,%4};"
                 :: "l"(addr), "f"(v.x), "f"(v.y), "f"(v.z), "f"(v.w)
                 : "memory");
}

template <int D>
__global__ void scatter_kernel(const float* __restrict__ feat,
                               const void* __restrict__ ei,
                               float* __restrict__ agg) {
    constexpr int C = D / 4;
    int idx = blockIdx.x * blockDim.x + threadIdx.x;
    if (idx >= N_EDGES * C) return;
    int e = idx / C;
    int c = idx - e * C;

    long long s, d;
    if (g_is64) {
        const long long* e64 = (const long long*)ei;
        s = e64[e];
        d = e64[N_EDGES + e];
    } else {
        const int* e32 = (const int*)ei;
        s = e32[e];
        d = e32[N_EDGES + e];
    }
    if ((unsigned long long)s >= N_NODES || (unsigned long long)d >= N_NODES) return;

    float4 v = __ldg(reinterpret_cast<const float4*>(feat + s * (long long)D) + c);
    red_add_v4(agg + d * (long long)D + c * 4, v);
}

// ---------------------------------------------------------------------------
// Fused 2-linear MLP with GIN add.
// blockDim = 256: two independent 128-thread row-groups share the staged
// weights. Each group processes RG=16 rows per tile iteration (amortizes the
// per-lane weight LDS traffic over 16 rows -> FMA-pipe bound, not crossbar).
// ---------------------------------------------------------------------------
template <int DIN, int DOUT>
__global__ void __launch_bounds__(256, 2)
mlp_kernel(const float* __restrict__ in,
           const float* __restrict__ agg,
           const float* __restrict__ Wa,
           const float* __restrict__ ba,
           const float* __restrict__ Wb,
           const float* __restrict__ bb,
           float* __restrict__ out) {
    constexpr int NG = 2;                 // row groups per block
    constexpr int RG = 16;                // rows per group
    constexpr int RT = NG * RG;           // rows per block tile = 32

    extern __shared__ float sm[];
    float* sWa  = sm;                     // DIN * 128
    float* sWb  = sWa + DIN * 128;        // 128 * DOUT
    float* sBa  = sWb + 128 * DOUT;       // 128
    float* sBb  = sBa + 128;              // DOUT
    float* sBuf = sBb + DOUT;             // RT * max(DIN,128)

    const int t  = threadIdx.x;           // 0..255
    const int g  = t >> 7;                // row group 0/1
    const int lt = t & 127;               // lane within group

    for (int i = t; i < DIN * 128 / 4; i += 256)
        reinterpret_cast<float4*>(sWa)[i] = reinterpret_cast<const float4*>(Wa)[i];
    for (int i = t; i < 128 * DOUT / 4; i += 256)
        reinterpret_cast<float4*>(sWb)[i] = reinterpret_cast<const float4*>(Wb)[i];
    if (t < 128) sBa[t] = ba[t];
    if (t < DOUT) sBb[t] = bb[t];
    __syncthreads();

    const int ntiles = (N_NODES + RT - 1) / RT;
    for (int tile = blockIdx.x; tile < ntiles; tile += gridDim.x) {
        const int r0 = tile * RT;

        // Load RT rows (GIN self + agg add) into sBuf [RT][DIN]
        for (int i = t; i < RT * DIN; i += 256) {
            int r = i / DIN, k = i - r * DIN;
            int row = r0 + r;
            float v = 0.f;
            if (row < N_NODES) {
                long long off = (long long)row * DIN + k;
                v = in[off] + agg[off];
            }
            sBuf[i] = v;
        }
        __syncthreads();

        // Phase 1: mid[lt] for RG rows of this group
        float acc[RG];
#pragma unroll
        for (int r = 0; r < RG; r++) acc[r] = sBa[lt];
#pragma unroll
        for (int k = 0; k < DIN; k += 4) {
            float w0 = sWa[(k + 0) * 128 + lt];
            float w1 = sWa[(k + 1) * 128 + lt];
            float w2 = sWa[(k + 2) * 128 + lt];
            float w3 = sWa[(k + 3) * 128 + lt];
#pragma unroll
            for (int r = 0; r < RG; r++) {
                float4 v = *reinterpret_cast<const float4*>(&sBuf[(g * RG + r) * DIN + k]);
                acc[r] += w0 * v.x;
                acc[r] += w1 * v.y;
                acc[r] += w2 * v.z;
                acc[r] += w3 * v.w;
            }
        }
        __syncthreads();   // reads of sBuf(rows) done before overwrite

        // mid = relu(acc) into sBuf (now [RT][128])
#pragma unroll
        for (int r = 0; r < RG; r++)
            sBuf[(g * RG + r) * 128 + lt] = fmaxf(acc[r], 0.f);
        __syncthreads();

        // Phase 2: out. For DOUT=64 split 128 group-threads into 2 subgroups.
        constexpr int G2  = 128 / DOUT;   // 1 or 2
        constexpr int RPG = RG / G2;      // 16 or 8
        const int grp = lt / DOUT;
        const int to  = lt - grp * DOUT;
        float acc2[RPG];
#pragma unroll
        for (int r = 0; r < RPG; r++) acc2[r] = sBb[to];
#pragma unroll
        for (int k = 0; k < 128; k += 4) {
            float w0 = sWb[(k + 0) * DOUT + to];
            float w1 = sWb[(k + 1) * DOUT + to];
            float w2 = sWb[(k + 2) * DOUT + to];
            float w3 = sWb[(k + 3) * DOUT + to];
#pragma unroll
            for (int r = 0; r < RPG; r++) {
                float4 v = *reinterpret_cast<const float4*>(
                    &sBuf[(g * RG + grp * RPG + r) * 128 + k]);
                acc2[r] += w0 * v.x;
                acc2[r] += w1 * v.y;
                acc2[r] += w2 * v.z;
                acc2[r] += w3 * v.w;
            }
        }
#pragma unroll
        for (int r = 0; r < RPG; r++) {
            int row = r0 + g * RG + grp * RPG + r;
            if (row < N_NODES)
                out[(long long)row * DOUT + to] = fmaxf(acc2[r], 0.f);
        }
        __syncthreads();
    }
}

// ---------------------------------------------------------------------------
extern "C" void kernel_launch(void* const* d_in, const int* in_sizes, int n_in,
                              void* d_out, int out_size) {
    const float* x   = (const float*)d_in[0];
    const void*  ei  = d_in[1];
    const float* W1a = (const float*)d_in[2];
    const float* b1a = (const float*)d_in[3];
    const float* W1b = (const float*)d_in[4];
    const float* b1b = (const float*)d_in[5];
    const float* W2a = (const float*)d_in[6];
    const float* b2a = (const float*)d_in[7];
    const float* W2b = (const float*)d_in[8];
    const float* b2b = (const float*)d_in[9];
    float*       out = (float*)d_out;

    float *agg1, *hmid, *agg2;
    cudaGetSymbolAddress((void**)&agg1, g_agg1);
    cudaGetSymbolAddress((void**)&hmid, g_hmid);
    cudaGetSymbolAddress((void**)&agg2, g_agg2);

    const int RT = 32;
    const int SMEM1 = (DI * 128 + 128 * DH + 128 + DH + RT * 128) * 4;  // ~113KB
    const int SMEM2 = (DH * 128 + 128 * DO + 128 + DO + RT * 128) * 4;  // ~112.8KB
    cudaFuncSetAttribute(mlp_kernel<DI, DH>,
                         cudaFuncAttributeMaxDynamicSharedMemorySize, SMEM1);
    cudaFuncSetAttribute(mlp_kernel<DH, DO>,
                         cudaFuncAttributeMaxDynamicSharedMemorySize, SMEM2);

    {
        int n2 = N_NODES * DH / 4;
        zero_kernel<<<(n2 + 255) / 256, 256>>>();
    }
    detect_kernel<<<(N_EDGES + 255) / 256, 256>>>(ei);
    {
        int total = N_EDGES * (DI / 4);
        scatter_kernel<DI><<<(total + 255) / 256, 256>>>(x, ei, agg1);
    }
    mlp_kernel<DI, DH><<<296, 256, SMEM1>>>(x, agg1, W1a, b1a, W1b, b1b, hmid);
    {
        int total = N_EDGES * (DH / 4);
        scatter_kernel<DH><<<(total + 255) / 256, 256>>>(hmid, ei, agg2);
    }
    mlp_kernel<DH, DO><<<296, 256, SMEM2>>>(hmid, agg2, W2a, b2a, W2b, b2b, out);
}

// round 5
// speedup vs baseline: 1.6253x; 1.1884x over previous
#include <cuda_runtime.h>
#include <cuda_bf16.h>
#include <cstdint>

// GIN 2-layer GNN for GB300 (sm_103a)
#define N_NODES 50000
#define N_EDGES 800000
#define DI 64
#define DH 128
#define DO 64

__device__ float4 g_agg1[N_NODES * DI / 4];
__device__ float4 g_hmid[N_NODES * DH / 4];
__device__ float4 g_agg2[N_NODES * DH / 4];
__device__ int    g_is64;

// ---------------------------------------------------------------------------
__global__ void zero_kernel() {
    int i = blockIdx.x * blockDim.x + threadIdx.x;
    if (i == 0) g_is64 = 1;
    const int n1 = N_NODES * DI / 4;
    const int n2 = N_NODES * DH / 4;
    float4 z = make_float4(0.f, 0.f, 0.f, 0.f);
    if (i < n1) g_agg1[i] = z;
    if (i < n2) g_agg2[i] = z;
}

__global__ void detect_kernel(const void* ei) {
    const long long* e64 = (const long long*)ei;
    int i = blockIdx.x * blockDim.x + threadIdx.x;
    if (i < N_EDGES) {
        long long v = e64[i];
        if (v < 0 || v >= N_NODES) g_is64 = 0;
    }
}

// ---------------------------------------------------------------------------
__device__ __forceinline__ void red_add_v4(float* addr, float4 v) {
    asm volatile("red.global.add.v4.f32 [%0], {%1,%2,%3,%4};"
                 :: "l"(addr), "f"(v.x), "f"(v.y), "f"(v.z), "f"(v.w)
                 : "memory");
}

template <int D>
__global__ void scatter_kernel(const float* __restrict__ feat,
                               const void* __restrict__ ei,
                               float* __restrict__ agg) {
    constexpr int C = D / 4;
    int idx = blockIdx.x * blockDim.x + threadIdx.x;
    if (idx >= N_EDGES * C) return;
    int e = idx / C;
    int c = idx - e * C;

    long long s, d;
    if (g_is64) {
        const long long* e64 = (const long long*)ei;
        s = e64[e];
        d = e64[N_EDGES + e];
    } else {
        const int* e32 = (const int*)ei;
        s = e32[e];
        d = e32[N_EDGES + e];
    }
    if ((unsigned long long)s >= N_NODES || (unsigned long long)d >= N_NODES) return;

    float4 v = __ldg(reinterpret_cast<const float4*>(feat + s * (long long)D) + c);
    red_add_v4(agg + d * (long long)D + c * 4, v);
}

// ---------------------------------------------------------------------------
// Packed f32x2 helpers
// ---------------------------------------------------------------------------
__device__ __forceinline__ unsigned long long ffma2(unsigned long long a,
                                                    unsigned long long b,
                                                    unsigned long long c) {
    unsigned long long d;
    asm("fma.rn.f32x2 %0, %1, %2, %3;" : "=l"(d) : "l"(a), "l"(b), "l"(c));
    return d;
}
__device__ __forceinline__ unsigned long long dup2(float x) {
    unsigned long long d;
    unsigned int u = __float_as_uint(x);
    asm("mov.b64 %0, {%1, %1};" : "=l"(d) : "r"(u));
    return d;
}
__device__ __forceinline__ void unpack2(unsigned long long v, float& lo, float& hi) {
    unsigned int a, b;
    asm("mov.b64 {%0, %1}, %2;" : "=r"(a), "=r"(b) : "l"(v));
    lo = __uint_as_float(a); hi = __uint_as_float(b);
}
__device__ __forceinline__ void lds_v2b64(uint32_t addr,
                                          unsigned long long& a,
                                          unsigned long long& b) {
    asm("ld.shared.v2.b64 {%0, %1}, [%2];" : "=l"(a), "=l"(b) : "r"(addr));
}

// ---------------------------------------------------------------------------
// Fused 2-linear MLP with GIN add; f32x2 packed row-pairs.
// blockDim=256 = 4 groups x 64 threads. Each group: RG=8 rows = P=4 pairs.
// Thread c in group handles output cols (2c, 2c+1).
// sBuf pair-packed: [pair q][k][half], half = row parity.
// ---------------------------------------------------------------------------
template <int DIN, int DOUT>
__global__ void __launch_bounds__(256, 2)
mlp_kernel(const float* __restrict__ in,
           const float* __restrict__ agg,
           const float* __restrict__ Wa,
           const float* __restrict__ ba,
           const float* __restrict__ Wb,
           const float* __restrict__ bb,
           float* __restrict__ out) {
    constexpr int NG = 4;                 // groups per block
    constexpr int P  = 4;                 // row pairs per group
    constexpr int RG = 2 * P;             // rows per group = 8
    constexpr int RT = NG * RG;           // rows per tile = 32
    constexpr int NP = RT / 2;            // pairs per tile = 16

    extern __shared__ float sm[];
    float* sWa  = sm;                     // DIN * 128
    float* sWb  = sWa + DIN * 128;        // 128 * DOUT
    float* sBuf = sWb + 128 * DOUT;       // RT * 128 floats (pair-packed rows / mid)

    const int t = threadIdx.x;            // 0..255
    const int g = t >> 6;                 // group 0..3
    const int c = t & 63;                 // col-pair index in group
    const int q0 = g * P;                 // first pair of this group

    // Stage weights
    for (int i = t; i < DIN * 128 / 4; i += 256)
        reinterpret_cast<float4*>(sWa)[i] = reinterpret_cast<const float4*>(Wa)[i];
    for (int i = t; i < 128 * DOUT / 4; i += 256)
        reinterpret_cast<float4*>(sWb)[i] = reinterpret_cast<const float4*>(Wb)[i];
    __syncthreads();

    // Phase-1 bias (cols 2c, 2c+1): dup into f32x2
    const float2 ba2 = __ldg(reinterpret_cast<const float2*>(ba + 2 * c));
    const unsigned long long ba0 = dup2(ba2.x), ba1 = dup2(ba2.y);

    // Phase-2 mapping
    constexpr int CP2 = DOUT / 2;         // col-pairs in phase 2 (64 or 32)
    constexpr int SUB = 64 / CP2;         // 1 or 2
    constexpr int P2  = P / SUB;          // pairs per thread in phase 2 (4 or 2)
    const int sub = c / CP2;
    const int cc  = c - sub * CP2;
    const int qb2 = q0 + sub * P2;
    const float2 bb2 = __ldg(reinterpret_cast<const float2*>(bb + 2 * cc));
    const unsigned long long bb0 = dup2(bb2.x), bb1 = dup2(bb2.y);

    const uint32_t sBufAddr = (uint32_t)__cvta_generic_to_shared(sBuf);

    const int ntiles = (N_NODES + RT - 1) / RT;
    for (int tile = blockIdx.x; tile < ntiles; tile += gridDim.x) {
        const int r0 = tile * RT;

        // Load RT rows (GIN self + agg) pair-packed into sBuf:
        // sBuf[q*(DIN*2) + k*2 + (r&1)]
        for (int i = t; i < RT * DIN; i += 256) {
            int r = i / DIN, k = i - r * DIN;
            int row = r0 + r;
            float v = 0.f;
            if (row < N_NODES) {
                long long off = (long long)row * DIN + k;
                v = in[off] + agg[off];
            }
            sBuf[(r >> 1) * (DIN * 2) + k * 2 + (r & 1)] = v;
        }
        __syncthreads();

        // ---- Phase 1: mid = relu(rows @ Wa + ba), mid dim = 128 ----
        unsigned long long acc[P][2];
#pragma unroll
        for (int p = 0; p < P; p++) { acc[p][0] = ba0; acc[p][1] = ba1; }

#pragma unroll
        for (int k = 0; k < DIN; k += 2) {
            float2 w0 = *reinterpret_cast<const float2*>(&sWa[k * 128 + 2 * c]);
            float2 w1 = *reinterpret_cast<const float2*>(&sWa[(k + 1) * 128 + 2 * c]);
            unsigned long long w0x = dup2(w0.x), w0y = dup2(w0.y);
            unsigned long long w1x = dup2(w1.x), w1y = dup2(w1.y);
#pragma unroll
            for (int p = 0; p < P; p++) {
                unsigned long long vk, vk1;
                lds_v2b64(sBufAddr + ((q0 + p) * (DIN * 2) + k * 2) * 4, vk, vk1);
                acc[p][0] = ffma2(w0x, vk, acc[p][0]);
                acc[p][1] = ffma2(w0y, vk, acc[p][1]);
                acc[p][0] = ffma2(w1x, vk1, acc[p][0]);
                acc[p][1] = ffma2(w1y, vk1, acc[p][1]);
            }
        }
        __syncthreads();   // done reading row data

        // relu + store mid pair-packed: sBuf[q*256 + col*2 + half]
#pragma unroll
        for (int p = 0; p < P; p++) {
            float a0, a1, b0, b1;
            unpack2(acc[p][0], a0, a1);
            unpack2(acc[p][1], b0, b1);
            float4 m;
            m.x = fmaxf(a0, 0.f); m.y = fmaxf(a1, 0.f);
            m.z = fmaxf(b0, 0.f); m.w = fmaxf(b1, 0.f);
            *reinterpret_cast<float4*>(&sBuf[(q0 + p) * 256 + 4 * c]) = m;
        }
        __syncthreads();

        // ---- Phase 2: out = relu(mid @ Wb + bb) ----
        unsigned long long acc2[P2][2];
#pragma unroll
        for (int p = 0; p < P2; p++) { acc2[p][0] = bb0; acc2[p][1] = bb1; }

#pragma unroll
        for (int k = 0; k < 128; k += 2) {
            float2 w0 = *reinterpret_cast<const float2*>(&sWb[k * DOUT + 2 * cc]);
            float2 w1 = *reinterpret_cast<const float2*>(&sWb[(k + 1) * DOUT + 2 * cc]);
            unsigned long long w0x = dup2(w0.x), w0y = dup2(w0.y);
            unsigned long long w1x = dup2(w1.x), w1y = dup2(w1.y);
#pragma unroll
            for (int p = 0; p < P2; p++) {
                unsigned long long vk, vk1;
                lds_v2b64(sBufAddr + ((qb2 + p) * 256 + k * 2) * 4, vk, vk1);
                acc2[p][0] = ffma2(w0x, vk, acc2[p][0]);
                acc2[p][1] = ffma2(w0y, vk, acc2[p][1]);
                acc2[p][0] = ffma2(w1x, vk1, acc2[p][0]);
                acc2[p][1] = ffma2(w1y, vk1, acc2[p][1]);
            }
        }

        // relu + store to global (rows 2q, 2q+1; cols 2cc, 2cc+1)
#pragma unroll
        for (int p = 0; p < P2; p++) {
            float a0, a1, b0, b1;
            unpack2(acc2[p][0], a0, a1);
            unpack2(acc2[p][1], b0, b1);
            int rowE = r0 + 2 * (qb2 + p);
            int rowO = rowE + 1;
            if (rowE < N_NODES) {
                float2 v; v.x = fmaxf(a0, 0.f); v.y = fmaxf(b0, 0.f);
                *reinterpret_cast<float2*>(&out[(long long)rowE * DOUT + 2 * cc]) = v;
            }
            if (rowO < N_NODES) {
                float2 v; v.x = fmaxf(a1, 0.f); v.y = fmaxf(b1, 0.f);
                *reinterpret_cast<float2*>(&out[(long long)rowO * DOUT + 2 * cc]) = v;
            }
        }
        __syncthreads();
    }
}

// ---------------------------------------------------------------------------
extern "C" void kernel_launch(void* const* d_in, const int* in_sizes, int n_in,
                              void* d_out, int out_size) {
    const float* x   = (const float*)d_in[0];
    const void*  ei  = d_in[1];
    const float* W1a = (const float*)d_in[2];
    const float* b1a = (const float*)d_in[3];
    const float* W1b = (const float*)d_in[4];
    const float* b1b = (const float*)d_in[5];
    const float* W2a = (const float*)d_in[6];
    const float* b2a = (const float*)d_in[7];
    const float* W2b = (const float*)d_in[8];
    const float* b2b = (const float*)d_in[9];
    float*       out = (float*)d_out;

    float *agg1, *hmid, *agg2;
    cudaGetSymbolAddress((void**)&agg1, g_agg1);
    cudaGetSymbolAddress((void**)&hmid, g_hmid);
    cudaGetSymbolAddress((void**)&agg2, g_agg2);

    const int RT = 32;
    const int SMEM1 = (DI * 128 + 128 * DH + RT * 128) * 4;  // ~113.0 KB
    const int SMEM2 = (DH * 128 + 128 * DO + RT * 128) * 4;  // ~112.0 KB
    cudaFuncSetAttribute(mlp_kernel<DI, DH>,
                         cudaFuncAttributeMaxDynamicSharedMemorySize, SMEM1);
    cudaFuncSetAttribute(mlp_kernel<DH, DO>,
                         cudaFuncAttributeMaxDynamicSharedMemorySize, SMEM2);

    {
        int n2 = N_NODES * DH / 4;
        zero_kernel<<<(n2 + 255) / 256, 256>>>();
    }
    detect_kernel<<<(N_EDGES + 255) / 256, 256>>>(ei);
    {
        int total = N_EDGES * (DI / 4);
        scatter_kernel<DI><<<(total + 255) / 256, 256>>>(x, ei, agg1);
    }
    mlp_kernel<DI, DH><<<296, 256, SMEM1>>>(x, agg1, W1a, b1a, W1b, b1b, hmid);
    {
        int total = N_EDGES * (DH / 4);
        scatter_kernel<DH><<<(total + 255) / 256, 256>>>(hmid, ei, agg2);
    }
    mlp_kernel<DH, DO><<<296, 256, SMEM2>>>(hmid, agg2, W2a, b2a, W2b, b2b, out);
}